// round 14
// baseline (speedup 1.0000x reference)
#include <cuda_runtime.h>
#include <cstdint>

#define T_STEPS 1024
#define NB 8192
#define NP 6
#define B1 8                          // steps per batch
#define NBT1 (T_STEPS / B1)           // 128 batches
#define STAGES 8                      // cp.async ring depth per compute warp
#define NBUF 4                        // staging ring depth (batches)
#define SMEM_BYTES 122880             // 120 KB: forces 1 block per SM
#define RING_WARP_FLOATS (STAGES * 3 * B1 * 32)   // 6144 floats = 24 KB/warp
#define STG_BUF_FLOATS (B1 * 8 * 64)  // one staging buffer: 64 rows x 64 basins = 16 KB

#define BAR_SYNC(id)   asm volatile("bar.sync %0, 128;"   :: "r"(id) : "memory")
#define BAR_ARRIVE(id) asm volatile("bar.arrive %0, 128;" :: "r"(id) : "memory")

struct Params {
    float Qmax, Df, Tmax, Tmin, Smax, invSmax, posf_l2, c0;
};

__device__ __forceinline__ float ex2_approx(float x)
{
    float y;
    asm("ex2.approx.ftz.f32 %0, %1;" : "=f"(y) : "f"(x));
    return y;
}

__device__ __forceinline__ Params load_params(const float* __restrict__ sp, int b)
{
    const float lo[NP] = {0.0f, 100.0f, 10.0f, 0.0f, 0.0f, -3.0f};
    const float hi[NP] = {0.1f, 1500.0f, 50.0f, 5.0f, 3.0f, 0.0f};
    float prm[NP];
#pragma unroll
    for (int i = 0; i < NP; i++) {
        float x = sp[b * NP + i];
        float s = 1.0f / (1.0f + __expf(-x));
        prm[i] = lo[i] + (hi[i] - lo[i]) * s;
    }
    Params q;
    q.Smax = prm[1]; q.Qmax = prm[2]; q.Df = prm[3];
    q.Tmax = prm[4]; q.Tmin = prm[5];
    q.invSmax = 1.0f / prm[1];
    const float negf_l2 = -prm[0] * 1.4426950408889634f;   // -f*log2(e)
    q.posf_l2 = -negf_l2;
    q.c0 = negf_l2 * prm[1];                                // -f*log2(e)*Smax
    return q;
}

__device__ __forceinline__ void cpasync16(unsigned int dst_smem, const float* src)
{
    asm volatile("cp.async.cg.shared.global [%0], [%1], 16;"
                 :: "r"(dst_smem), "l"(src));
}
__device__ __forceinline__ void cp_commit()
{
    asm volatile("cp.async.commit_group;" ::: "memory");
}
template <int N>
__device__ __forceinline__ void cp_wait()
{
    asm volatile("cp.async.wait_group %0;" :: "n"(N) : "memory");
}

// Warp-specialized direct-store scan, decoupled via 4-deep staging ring:
//   warps 0-1: serial EXP-HYDRO chains (64 basins) -> smem staging (STS only)
//   warps 2-3: drain staging -> GMEM (LDS.128 + STG.128) on their own SMSPs
// Named barriers: FILLED[j]=1+j (compute arrive, storer sync),
//                 DRAINED[j]=5+j (storer arrive, compute sync before reuse).
// Compute never blocks in steady state (drain is ~3x faster than fill).
__global__ void __launch_bounds__(128)
hydro_ws2(const float* __restrict__ prcp,
          const float* __restrict__ temp,
          const float* __restrict__ pet,
          const float* __restrict__ sp,
          float* __restrict__ out)
{
    extern __shared__ float sm[];

    const int tid  = threadIdx.x;
    const int w    = tid >> 5;
    const int lane = tid & 31;
    const int bb   = blockIdx.x * 64;       // block's basin base (64 basins)

    float* staging = sm + 2 * RING_WARP_FLOATS;   // NBUF x 4096 floats

    if (w < 2) {
        // ===================== compute warps =====================
        const int b     = bb + w * 32 + lane;
        const int wbase = bb + w * 32;
        const Params q  = load_params(sp, b);

        float* wring = sm + w * RING_WARP_FLOATS;

        const float* vp0 = prcp + wbase;
        const float* vp1 = temp + wbase;
        const float* vp2 = pet  + wbase;

        // cooperative vectorized fill: 24 rows of 128B per batch -> 192 x 16B
        const int seg = lane & 7;
        const int r0  = lane >> 3;
        auto issue = [&](int batch, int s) {
            const int bc = (batch < NBT1) ? batch : NBT1 - 1;
            const size_t tbase = (size_t)bc * B1 * NB;
#pragma unroll
            for (int j = 0; j < 6; j++) {
                const int row = r0 + 4 * j;            // 0..23
                const int a   = row >> 3;              // forcing array
                const int i   = row & 7;               // step within batch
                const float* src = (a == 0 ? vp0 : (a == 1 ? vp1 : vp2))
                                 + tbase + (size_t)i * NB + seg * 4;
                unsigned int dst = (unsigned int)__cvta_generic_to_shared(
                    wring + ((s * 3 + a) * B1 + i) * 32 + seg * 4);
                cpasync16(dst, src);
            }
            cp_commit();
        };

#pragma unroll
        for (int s = 0; s < STAGES - 1; s++)
            issue(s, s);

        float snow = 0.0f, soil = 0.0f;

        for (int tb = 0; tb < NBT1; tb++) {
            issue(tb + STAGES - 1, (tb + STAGES - 1) % STAGES);
            cp_wait<STAGES - 1>();
            __syncwarp();

            // reuse staging slot tb%NBUF: wait until its batch tb-NBUF drained
            if (tb >= NBUF) BAR_SYNC(5 + (tb & (NBUF - 1)));

            const int s = tb % STAGES;
            const float* rs = wring + s * 3 * B1 * 32;
            float* sb = staging + (tb & (NBUF - 1)) * STG_BUF_FLOATS + w * 32 + lane;

#pragma unroll
            for (int i = 0; i < B1; i++) {
                const float p  = rs[(0 * B1 + i) * 32 + lane];
                const float tm = rs[(1 * B1 + i) * 32 + lane];
                const float pe = rs[(2 * B1 + i) * 32 + lane];

                const float snowfall    = (tm < q.Tmin) ? p : 0.0f;
                const float rainfall    = p - snowfall;
                const float melt        = fminf(snow, q.Df * fmaxf(tm - q.Tmax, 0.0f));
                const float evap        = pe * fminf(soil * q.invSmax, 1.0f);
                const float baseflow    = q.Qmax *
                    ex2_approx(fminf(fmaf(q.posf_l2, soil, q.c0), 0.0f));
                const float surfaceflow = fmaxf(soil - q.Smax, 0.0f);

                const float d_snow = snowfall - melt;
                const float d_soil = rainfall + melt - evap - baseflow - surfaceflow;

                snow = fmaxf(snow + d_snow, 1e-6f);
                soil = fmaxf(soil + d_soil, 1e-6f);

                sb[(i * 8 + 0) * 64] = snowfall;
                sb[(i * 8 + 1) * 64] = rainfall;
                sb[(i * 8 + 2) * 64] = melt;
                sb[(i * 8 + 3) * 64] = evap;
                sb[(i * 8 + 4) * 64] = baseflow;
                sb[(i * 8 + 5) * 64] = surfaceflow;
                sb[(i * 8 + 6) * 64] = d_snow;
                sb[(i * 8 + 7) * 64] = d_soil;
            }
            // publish buffer tb (non-blocking for the chain)
            BAR_ARRIVE(1 + (tb & (NBUF - 1)));
        }
    } else {
        // ===================== storer warps =====================
        // warp 2 -> rows 0..31, warp 3 -> rows 32..63 of each 64-row batch.
        // lanes 0-15 cover row r, lanes 16-31 row r+1 (512B per LDS/STG pair).
        const int wofs = (w - 2) * 32;
        const int half = lane >> 4;          // 0/1
        const int col  = lane & 15;

        for (int tb = 0; tb < NBT1; tb++) {
            BAR_SYNC(1 + (tb & (NBUF - 1)));            // wait buffer tb filled

            const float* sb = staging + (tb & (NBUF - 1)) * STG_BUF_FLOATS
                            + (wofs + half) * 64 + col * 4;
            float* g = out + ((size_t)tb * 64 + wofs + half) * NB + bb + col * 4;
#pragma unroll
            for (int k = 0; k < 16; k++) {
                const float4 v = *reinterpret_cast<const float4*>(sb + k * 128);
                __stcs(reinterpret_cast<float4*>(g), v);
                g += 2 * NB;
            }

            if (tb + NBUF < NBT1)                        // slot will be reused
                BAR_ARRIVE(5 + (tb & (NBUF - 1)));
        }
    }
}

extern "C" void kernel_launch(void* const* d_in, const int* in_sizes, int n_in,
                              void* d_out, int out_size)
{
    const float* prcp = (const float*)d_in[0];
    const float* temp = (const float*)d_in[1];
    const float* pet  = (const float*)d_in[2];
    const float* sp   = (const float*)d_in[3];
    float* out = (float*)d_out;

    cudaFuncSetAttribute(hydro_ws2,
                         cudaFuncAttributeMaxDynamicSharedMemorySize, SMEM_BYTES);

    // 128 blocks x 128 threads: 1 block/SM, 2 compute + 2 storer warps per SM.
    // 4-deep staging ring + named barriers keep the serial chains decoupled
    // from store drain; store issue lives on the otherwise-idle SMSPs.
    hydro_ws2<<<128, 128, SMEM_BYTES>>>(prcp, temp, pet, sp, out);
}

// round 15
// speedup vs baseline: 1.1855x; 1.1855x over previous
#include <cuda_runtime.h>
#include <cstdint>

#define T_STEPS 1024
#define NB 8192
#define NP 6
#define B1 8                         // batch (steps per pipeline stage)
#define NBT1 (T_STEPS / B1)          // 128 batches
#define STAGES 8                     // cp.async ring depth per warp
#define SMEM_BYTES 122880            // 120 KB: forces 1 block per SM
#define RING_WARP_FLOATS (STAGES * 3 * B1 * 32)   // 6144 floats = 24 KB/warp (x4 = 96 KB)

struct Params {
    float Qmax, Df, Tmax, Tmin, Smax, invSmax, posf_l2, c0;
};

__device__ __forceinline__ float ex2_approx(float x)
{
    float y;
    asm("ex2.approx.ftz.f32 %0, %1;" : "=f"(y) : "f"(x));
    return y;
}

__device__ __forceinline__ Params load_params(const float* __restrict__ sp, int b)
{
    const float lo[NP] = {0.0f, 100.0f, 10.0f, 0.0f, 0.0f, -3.0f};
    const float hi[NP] = {0.1f, 1500.0f, 50.0f, 5.0f, 3.0f, 0.0f};
    float prm[NP];
#pragma unroll
    for (int i = 0; i < NP; i++) {
        float x = sp[b * NP + i];
        float s = 1.0f / (1.0f + __expf(-x));
        prm[i] = lo[i] + (hi[i] - lo[i]) * s;
    }
    Params q;
    q.Smax = prm[1]; q.Qmax = prm[2]; q.Df = prm[3];
    q.Tmax = prm[4]; q.Tmin = prm[5];
    q.invSmax = 1.0f / prm[1];
    const float negf_l2 = -prm[0] * 1.4426950408889634f;   // -f*log2(e)
    q.posf_l2 = -negf_l2;
    q.c0 = negf_l2 * prm[1];                                // -f*log2(e)*Smax
    return q;
}

__device__ __forceinline__ void cpasync16(unsigned int dst_smem, const float* src)
{
    asm volatile("cp.async.cg.shared.global [%0], [%1], 16;"
                 :: "r"(dst_smem), "l"(src));
}
__device__ __forceinline__ void cp_commit()
{
    asm volatile("cp.async.commit_group;" ::: "memory");
}
template <int N>
__device__ __forceinline__ void cp_wait()
{
    asm volatile("cp.async.wait_group %0;" :: "n"(N) : "memory");
}

// Duplicate-chain direct-store scan:
//   4 warps/SM, one per SMSP. Warp w handles basin half (w&1) with batch
//   parity (w>>1): warps 0,1 store even batches, warps 2,3 recompute the
//   IDENTICAL chains (bit-identical FP) and store odd batches. Store issue
//   per warp halves; warps are fully independent (own ring, own cp.async
//   groups) -> zero barriers. Duplicate forcing reads coalesce in L2.
__global__ void __launch_bounds__(128)
hydro_dup(const float* __restrict__ prcp,
          const float* __restrict__ temp,
          const float* __restrict__ pet,
          const float* __restrict__ sp,
          float* __restrict__ out)
{
    extern __shared__ float smem_dyn[];

    const int tid   = threadIdx.x;
    const int w     = tid >> 5;
    const int lane  = tid & 31;
    const int g     = w & 1;            // basin half within block's 64 basins
    const int par   = w >> 1;           // batch parity this warp stores
    const int bb    = blockIdx.x * 64;
    const int b     = bb + g * 32 + lane;
    const int wbase = bb + g * 32;
    const Params q  = load_params(sp, b);

    float* wring = smem_dyn + w * RING_WARP_FLOATS;

    const float* vp0 = prcp + wbase;
    const float* vp1 = temp + wbase;
    const float* vp2 = pet  + wbase;

    // cooperative vectorized fill: 24 rows of 128B per batch -> 192 x 16B
    // lane l handles seg = l&7, rows (l>>3)+4j, j=0..5
    const int seg = lane & 7;
    const int r0  = lane >> 3;
    auto issue = [&](int batch, int s) {
        const int bc = (batch < NBT1) ? batch : NBT1 - 1;
        const size_t tbase = (size_t)bc * B1 * NB;
#pragma unroll
        for (int j = 0; j < 6; j++) {
            const int row = r0 + 4 * j;            // 0..23
            const int a   = row >> 3;              // forcing array
            const int i   = row & 7;               // step within batch
            const float* src = (a == 0 ? vp0 : (a == 1 ? vp1 : vp2))
                             + tbase + (size_t)i * NB + seg * 4;
            unsigned int dst = (unsigned int)__cvta_generic_to_shared(
                wring + ((s * 3 + a) * B1 + i) * 32 + seg * 4);
            cpasync16(dst, src);
        }
        cp_commit();
    };

#pragma unroll
    for (int s = 0; s < STAGES - 1; s++)
        issue(s, s);

    float snow = 0.0f, soil = 0.0f;
    float* o = out + b;                 // [T, 8, B] walk

    for (int tb = 0; tb < NBT1; tb++) {
        issue(tb + STAGES - 1, (tb + STAGES - 1) % STAGES);
        cp_wait<STAGES - 1>();
        __syncwarp();

        const bool do_store = ((tb & 1) == par);
        const int s = tb % STAGES;
        const float* rs = wring + s * 3 * B1 * 32;

#pragma unroll
        for (int i = 0; i < B1; i++) {
            const float p  = rs[(0 * B1 + i) * 32 + lane];
            const float tm = rs[(1 * B1 + i) * 32 + lane];
            const float pe = rs[(2 * B1 + i) * 32 + lane];

            const float snowfall    = (tm < q.Tmin) ? p : 0.0f;
            const float rainfall    = p - snowfall;
            const float melt        = fminf(snow, q.Df * fmaxf(tm - q.Tmax, 0.0f));
            const float evap        = pe * fminf(soil * q.invSmax, 1.0f);
            const float baseflow    = q.Qmax *
                ex2_approx(fminf(fmaf(q.posf_l2, soil, q.c0), 0.0f));
            const float surfaceflow = fmaxf(soil - q.Smax, 0.0f);

            const float d_snow = snowfall - melt;
            const float d_soil = rainfall + melt - evap - baseflow - surfaceflow;

            snow = fmaxf(snow + d_snow, 1e-6f);
            soil = fmaxf(soil + d_soil, 1e-6f);

            if (do_store) {
                __stcs(o + 0 * NB, snowfall);
                __stcs(o + 1 * NB, rainfall);
                __stcs(o + 2 * NB, melt);
                __stcs(o + 3 * NB, evap);
                __stcs(o + 4 * NB, baseflow);
                __stcs(o + 5 * NB, surfaceflow);
                __stcs(o + 6 * NB, d_snow);
                __stcs(o + 7 * NB, d_soil);
            }
            o += 8 * NB;
        }
    }
}

extern "C" void kernel_launch(void* const* d_in, const int* in_sizes, int n_in,
                              void* d_out, int out_size)
{
    const float* prcp = (const float*)d_in[0];
    const float* temp = (const float*)d_in[1];
    const float* pet  = (const float*)d_in[2];
    const float* sp   = (const float*)d_in[3];
    float* out = (float*)d_out;

    cudaFuncSetAttribute(hydro_dup,
                         cudaFuncAttributeMaxDynamicSharedMemorySize, SMEM_BYTES);

    // 128 blocks x 128 threads: 1 block/SM (120 KB smem), 4 warps on 4 SMSPs.
    // Chains duplicated across parity pairs; store issue split per parity.
    hydro_dup<<<128, 128, SMEM_BYTES>>>(prcp, temp, pet, sp, out);
}